// round 9
// baseline (speedup 1.0000x reference)
#include <cuda_runtime.h>
#include <cuda_fp16.h>
#include <cstdint>

// RoutingLinear == GEMM + bias: O[t][v] = sum_d X[t][d]*W[v][d] + b[v]
// X[2048,4096] fp32, W[32000,4096] fp32, b[32000], O[2048,32000] fp32.
//
// R8 post-mortem: BK=64/3-stage regressed the GEMM (smem 110.6KB broke 2-CTA
// residency + shallower prefetch). R9: revert to the validated R7 skeleton
// (BK=32, 4-stage, 80KB smem), keep R8's fast MLP=4 conv kernels, and switch
// the MMA to fp16 ACCUMULATION (historically 2x issue rate vs f32-accum):
//   - each BK=32 chunk accumulated in fp16 (C=0 for first k-step),
//   - promoted into fp32 master accumulators every iteration.
// Error: ~2 roundings/chunk -> accum ~1.7e-4; RSS w/ 2e-4 quant -> ~2.6e-4.

#define NTHR 256
#define BM 128
#define BN 128
#define BK 32
#define STAGES 4
#define TS 40                        // smem row stride in halfs (32 + 8 pad)
#define TILE_BYTES (BM * TS * 2)     // 10240
#define STAGE_BYTES (2 * TILE_BYTES) // A, B
#define SMEM_NEED (STAGES * STAGE_BYTES)  // 81920

#define T_MAX 2048
#define D_MAX 4096
#define V_MAX 32000

// ---------------- scratch (static device memory; no allocs allowed) ----------
__device__ __half g_Xh[(size_t)T_MAX * D_MAX];
__device__ __half g_Wh[(size_t)V_MAX * D_MAX];

// ---------------- helpers -----------------------------------------------------
__device__ __forceinline__ uint32_t smem_u32_of(const void* p) {
    uint32_t a;
    asm("{ .reg .u64 t; cvta.to.shared.u64 t, %1; cvt.u32.u64 %0, t; }"
        : "=r"(a) : "l"(p));
    return a;
}
__device__ __forceinline__ void cp_async16(uint32_t dst, const void* src) {
    asm volatile("cp.async.cg.shared.global [%0], [%1], 16;"
                 :: "r"(dst), "l"(src) : "memory");
}
__device__ __forceinline__ void ldmatrix_x4(uint32_t& r0, uint32_t& r1,
                                            uint32_t& r2, uint32_t& r3,
                                            uint32_t addr) {
    asm volatile("ldmatrix.sync.aligned.m8n8.x4.shared.b16 {%0,%1,%2,%3}, [%4];"
                 : "=r"(r0), "=r"(r1), "=r"(r2), "=r"(r3) : "r"(addr));
}
// D(f16x2 pair) = A*B + C, with explicit C (used with C=0 to start a chunk)
__device__ __forceinline__ void mma_f16acc_init(uint32_t* d, const uint32_t* a,
                                                const uint32_t* b,
                                                uint32_t c0, uint32_t c1) {
    asm volatile(
        "mma.sync.aligned.m16n8k16.row.col.f16.f16.f16.f16 "
        "{%0,%1}, {%2,%3,%4,%5}, {%6,%7}, {%8,%9};"
        : "=r"(d[0]), "=r"(d[1])
        : "r"(a[0]), "r"(a[1]), "r"(a[2]), "r"(a[3]),
          "r"(b[0]), "r"(b[1]), "r"(c0), "r"(c1));
}
// D += A*B (in-place fp16 accumulate)
__device__ __forceinline__ void mma_f16acc(uint32_t* d, const uint32_t* a,
                                           const uint32_t* b) {
    asm volatile(
        "mma.sync.aligned.m16n8k16.row.col.f16.f16.f16.f16 "
        "{%0,%1}, {%2,%3,%4,%5}, {%6,%7}, {%0,%1};"
        : "+r"(d[0]), "+r"(d[1])
        : "r"(a[0]), "r"(a[1]), "r"(a[2]), "r"(a[3]),
          "r"(b[0]), "r"(b[1]));
}

// ---------------- convert kernels (MLP=4; grid*NTHR*4 == n4 exactly) -----------
__global__ void conv_X_kernel(const float4* __restrict__ src, long n4) {
    uint2* __restrict__ dst = reinterpret_cast<uint2*>(g_Xh);
    const long base = (long)blockIdx.x * (NTHR * 4) + threadIdx.x;
    float4 v[4];
#pragma unroll
    for (int k = 0; k < 4; ++k) v[k] = src[base + k * NTHR];
#pragma unroll
    for (int k = 0; k < 4; ++k) {
        __half2 h0 = __floats2half2_rn(v[k].x, v[k].y);
        __half2 h1 = __floats2half2_rn(v[k].z, v[k].w);
        dst[base + k * NTHR] = make_uint2(*(uint32_t*)&h0, *(uint32_t*)&h1);
    }
}
__global__ void conv_W_kernel(const float4* __restrict__ src, long n4) {
    uint2* __restrict__ dst = reinterpret_cast<uint2*>(g_Wh);
    const long base = (long)blockIdx.x * (NTHR * 4) + threadIdx.x;
    float4 v[4];
#pragma unroll
    for (int k = 0; k < 4; ++k) v[k] = src[base + k * NTHR];
#pragma unroll
    for (int k = 0; k < 4; ++k) {
        __half2 h0 = __floats2half2_rn(v[k].x, v[k].y);
        __half2 h1 = __floats2half2_rn(v[k].z, v[k].w);
        dst[base + k * NTHR] = make_uint2(*(uint32_t*)&h0, *(uint32_t*)&h1);
    }
}

// ---------------- GEMM ----------------------------------------------------------
__global__ __launch_bounds__(NTHR, 1)
void gemm_f16_kernel(const float* __restrict__ Bv,
                     float* __restrict__ O,
                     int T, int V, int K) {
    extern __shared__ char smem[];
    const uint32_t sbase = smem_u32_of(smem);

    const int tid  = threadIdx.x;
    const int wid  = tid >> 5;
    const int lane = tid & 31;
    const int wm   = wid & 3;      // 4 m-groups of 32 rows
    const int wn   = wid >> 2;     // 2 n-groups of 64 cols
    const int mtile = blockIdx.x;
    const int ntile = blockIdx.y;

    // ---- gmem sources for cp.async staging ----
    const int srow = tid >> 1;           // 0..127
    const int shalf = (tid & 1) * 16;    // half-element offset within 32-elem row
    const __half* gA = g_Xh + (size_t)(mtile * BM + srow) * K + shalf;
    const __half* gB = g_Wh + (size_t)(ntile * BN + srow) * K + shalf;
    const uint32_t sdst = (uint32_t)(srow * (TS * 2) + (tid & 1) * 32);

    // ---- ldmatrix per-lane base offsets (bytes) ----
    const int a_row = wm * 32 + (lane & 7) + ((lane >> 3) & 1) * 8;
    const uint32_t a_off = (uint32_t)(a_row * (TS * 2) + (lane >> 4) * 16);
    const int b_row = wn * 64 + (lane & 7) + ((lane >> 4) & 1) * 8;
    const uint32_t b_off = (uint32_t)(b_row * (TS * 2) + ((lane >> 3) & 1) * 16);

    float acc[2][8][4];                 // fp32 master accumulators
#pragma unroll
    for (int i = 0; i < 2; ++i)
#pragma unroll
        for (int j = 0; j < 8; ++j)
#pragma unroll
            for (int c = 0; c < 4; ++c) acc[i][j][c] = 0.f;

    const int KT = K / BK;  // 128

    auto issue_stage = [&](int t) {
        const uint32_t st = sbase + (uint32_t)(t % STAGES) * STAGE_BYTES + sdst;
        const size_t kb = (size_t)t * BK;
        const __half* s0 = gA + kb;
        const __half* s1 = gB + kb;
        cp_async16(st + 0 * TILE_BYTES,      s0);
        cp_async16(st + 0 * TILE_BYTES + 16, s0 + 8);
        cp_async16(st + 1 * TILE_BYTES,      s1);
        cp_async16(st + 1 * TILE_BYTES + 16, s1 + 8);
        asm volatile("cp.async.commit_group;" ::: "memory");
    };

    issue_stage(0);
    issue_stage(1);
    issue_stage(2);

    for (int t = 0; t < KT; ++t) {
        asm volatile("cp.async.wait_group 2;" ::: "memory");
        __syncthreads();
        if (t + 3 < KT) issue_stage(t + 3);

        const uint32_t st = sbase + (uint32_t)(t % STAGES) * STAGE_BYTES;
        const uint32_t aAdr = st + 0 * TILE_BYTES + a_off;
        const uint32_t bAdr = st + 1 * TILE_BYTES + b_off;

        uint32_t acc16[2][8][2];        // fp16x2 chunk accumulators (this iter)

#pragma unroll
        for (int ks = 0; ks < 2; ++ks) {
            const uint32_t koff = (uint32_t)(ks * 32);  // 16 halfs = 32B
            uint32_t af[2][4];
            ldmatrix_x4(af[0][0], af[0][1], af[0][2], af[0][3], aAdr + koff);
            ldmatrix_x4(af[1][0], af[1][1], af[1][2], af[1][3],
                        aAdr + koff + 16 * (TS * 2));
            uint32_t bf[4][4];
#pragma unroll
            for (int jp = 0; jp < 4; ++jp)
                ldmatrix_x4(bf[jp][0], bf[jp][1], bf[jp][2], bf[jp][3],
                            bAdr + koff + (uint32_t)(jp * 16 * (TS * 2)));
#pragma unroll
            for (int im = 0; im < 2; ++im)
#pragma unroll
                for (int jn = 0; jn < 8; ++jn) {
                    uint32_t breg[2] = { bf[jn >> 1][(jn & 1) * 2],
                                         bf[jn >> 1][(jn & 1) * 2 + 1] };
                    if (ks == 0)
                        mma_f16acc_init(acc16[im][jn], af[im], breg, 0u, 0u);
                    else
                        mma_f16acc(acc16[im][jn], af[im], breg);
                }
        }

        // promote fp16 chunk into fp32 masters (alu/fma pipes, hidden under HMMA)
#pragma unroll
        for (int im = 0; im < 2; ++im)
#pragma unroll
            for (int jn = 0; jn < 8; ++jn) {
                __half2 p0 = *reinterpret_cast<__half2*>(&acc16[im][jn][0]);
                __half2 p1 = *reinterpret_cast<__half2*>(&acc16[im][jn][1]);
                acc[im][jn][0] += __low2float(p0);
                acc[im][jn][1] += __high2float(p0);
                acc[im][jn][2] += __low2float(p1);
                acc[im][jn][3] += __high2float(p1);
            }
        __syncthreads();
    }

    // ---- epilogue: bias + store ----
    const int r_base = mtile * BM + wm * 32 + (lane >> 2);
    const int c_base = ntile * BN + wn * 64 + (lane & 3) * 2;
#pragma unroll
    for (int im = 0; im < 2; ++im) {
#pragma unroll
        for (int jn = 0; jn < 8; ++jn) {
            const int col = c_base + jn * 8;
            const float2 bv = *reinterpret_cast<const float2*>(Bv + col);
            const int r0 = r_base + im * 16;
            float2 o0 = make_float2(acc[im][jn][0] + bv.x, acc[im][jn][1] + bv.y);
            float2 o1 = make_float2(acc[im][jn][2] + bv.x, acc[im][jn][3] + bv.y);
            *reinterpret_cast<float2*>(O + (size_t)r0 * V + col)       = o0;
            *reinterpret_cast<float2*>(O + (size_t)(r0 + 8) * V + col) = o1;
        }
    }
}

// ---------------- launch --------------------------------------------------------
extern "C" void kernel_launch(void* const* d_in, const int* in_sizes, int n_in,
                              void* d_out, int out_size) {
    const float* X  = (const float*)d_in[0];  // [T, D]
    const float* W  = (const float*)d_in[1];  // [V, D]
    const float* Bv = (const float*)d_in[2];  // [V]
    float* O = (float*)d_out;                 // [T, V]

    const int V = in_sizes[2];
    const int D = in_sizes[1] / V;
    const int T = in_sizes[0] / D;

    const long nx4 = (long)T * D / 4;
    const long nw4 = (long)V * D / 4;
    conv_W_kernel<<<(unsigned)(nw4 / (NTHR * 4)), NTHR>>>((const float4*)W, nw4);
    conv_X_kernel<<<(unsigned)(nx4 / (NTHR * 4)), NTHR>>>((const float4*)X, nx4);

    cudaFuncSetAttribute(gemm_f16_kernel,
                         cudaFuncAttributeMaxDynamicSharedMemorySize, SMEM_NEED);
    dim3 grid(T / BM, V / BN);  // (16, 250); x fastest -> W tile reuse in L2
    gemm_f16_kernel<<<grid, NTHR, SMEM_NEED>>>(Bv, O, T, V, D);
}

// round 10
// speedup vs baseline: 1.5233x; 1.5233x over previous
#include <cuda_runtime.h>
#include <cuda_fp16.h>
#include <cstdint>

// RoutingLinear == GEMM + bias: O[t][v] = sum_d X[t][d]*W[v][d] + b[v]
// X[2048,4096] fp32, W[32000,4096] fp32, b[32000], O[2048,32000] fp32.
//
// R9 post-mortem: fp16-accumulate HMMA is NOT double-rate on sm_103a
// (2956us, refuted). R10 = composition of the two measured-best pieces:
//   - GEMM: R7 skeleton verbatim — fp16 in, FP32 accumulate, BM=BN=128,
//     BK=32, 4-stage cp.async, 8 warps (4m x 2n), 80KB smem, 2 CTAs/SM.
//     Measured at the legacy-HMMA roofline (~512 MAC/cyc/SM).
//   - Convs: R8 MLP=4 version (conv_W 106us @ 88% DRAM).
// Expected: ~1830us, rel_err 2.93e-4.

#define NTHR 256
#define BM 128
#define BN 128
#define BK 32
#define STAGES 4
#define TS 40                        // smem row stride in halfs (32 + 8 pad)
#define TILE_BYTES (BM * TS * 2)     // 10240
#define STAGE_BYTES (2 * TILE_BYTES) // A, B
#define SMEM_NEED (STAGES * STAGE_BYTES)  // 81920

#define T_MAX 2048
#define D_MAX 4096
#define V_MAX 32000

// ---------------- scratch (static device memory; no allocs allowed) ----------
__device__ __half g_Xh[(size_t)T_MAX * D_MAX];
__device__ __half g_Wh[(size_t)V_MAX * D_MAX];

// ---------------- helpers -----------------------------------------------------
__device__ __forceinline__ uint32_t smem_u32_of(const void* p) {
    uint32_t a;
    asm("{ .reg .u64 t; cvta.to.shared.u64 t, %1; cvt.u32.u64 %0, t; }"
        : "=r"(a) : "l"(p));
    return a;
}
__device__ __forceinline__ void cp_async16(uint32_t dst, const void* src) {
    asm volatile("cp.async.cg.shared.global [%0], [%1], 16;"
                 :: "r"(dst), "l"(src) : "memory");
}
__device__ __forceinline__ void ldmatrix_x4(uint32_t& r0, uint32_t& r1,
                                            uint32_t& r2, uint32_t& r3,
                                            uint32_t addr) {
    asm volatile("ldmatrix.sync.aligned.m8n8.x4.shared.b16 {%0,%1,%2,%3}, [%4];"
                 : "=r"(r0), "=r"(r1), "=r"(r2), "=r"(r3) : "r"(addr));
}
__device__ __forceinline__ void mma_f16(float* d, const uint32_t* a,
                                        const uint32_t* b) {
    asm volatile(
        "mma.sync.aligned.m16n8k16.row.col.f32.f16.f16.f32 "
        "{%0,%1,%2,%3}, {%4,%5,%6,%7}, {%8,%9}, {%0,%1,%2,%3};"
        : "+f"(d[0]), "+f"(d[1]), "+f"(d[2]), "+f"(d[3])
        : "r"(a[0]), "r"(a[1]), "r"(a[2]), "r"(a[3]), "r"(b[0]), "r"(b[1]));
}

// ---------------- convert kernels (MLP=4; grid*NTHR*4 == n4 exactly) -----------
__global__ void conv_X_kernel(const float4* __restrict__ src, long n4) {
    uint2* __restrict__ dst = reinterpret_cast<uint2*>(g_Xh);
    const long base = (long)blockIdx.x * (NTHR * 4) + threadIdx.x;
    float4 v[4];
#pragma unroll
    for (int k = 0; k < 4; ++k) v[k] = src[base + k * NTHR];
#pragma unroll
    for (int k = 0; k < 4; ++k) {
        __half2 h0 = __floats2half2_rn(v[k].x, v[k].y);
        __half2 h1 = __floats2half2_rn(v[k].z, v[k].w);
        dst[base + k * NTHR] = make_uint2(*(uint32_t*)&h0, *(uint32_t*)&h1);
    }
}
__global__ void conv_W_kernel(const float4* __restrict__ src, long n4) {
    uint2* __restrict__ dst = reinterpret_cast<uint2*>(g_Wh);
    const long base = (long)blockIdx.x * (NTHR * 4) + threadIdx.x;
    float4 v[4];
#pragma unroll
    for (int k = 0; k < 4; ++k) v[k] = src[base + k * NTHR];
#pragma unroll
    for (int k = 0; k < 4; ++k) {
        __half2 h0 = __floats2half2_rn(v[k].x, v[k].y);
        __half2 h1 = __floats2half2_rn(v[k].z, v[k].w);
        dst[base + k * NTHR] = make_uint2(*(uint32_t*)&h0, *(uint32_t*)&h1);
    }
}

// ---------------- GEMM (R7 skeleton, verbatim) ----------------------------------
__global__ __launch_bounds__(NTHR, 2)
void gemm_f16_kernel(const float* __restrict__ Bv,
                     float* __restrict__ O,
                     int T, int V, int K) {
    extern __shared__ char smem[];
    const uint32_t sbase = smem_u32_of(smem);

    const int tid  = threadIdx.x;
    const int wid  = tid >> 5;
    const int lane = tid & 31;
    const int wm   = wid & 3;      // 4 m-groups of 32 rows
    const int wn   = wid >> 2;     // 2 n-groups of 64 cols
    const int mtile = blockIdx.x;
    const int ntile = blockIdx.y;

    // ---- gmem sources for cp.async staging ----
    const int srow = tid >> 1;           // 0..127
    const int shalf = (tid & 1) * 16;    // half-element offset within 32-elem row
    const __half* gA = g_Xh + (size_t)(mtile * BM + srow) * K + shalf;
    const __half* gB = g_Wh + (size_t)(ntile * BN + srow) * K + shalf;
    const uint32_t sdst = (uint32_t)(srow * (TS * 2) + (tid & 1) * 32);

    // ---- ldmatrix per-lane base offsets (bytes, relative to tile base) ----
    const int a_row = wm * 32 + (lane & 7) + ((lane >> 3) & 1) * 8;
    const uint32_t a_off = (uint32_t)(a_row * (TS * 2) + (lane >> 4) * 16);
    const int b_row = wn * 64 + (lane & 7) + ((lane >> 4) & 1) * 8;
    const uint32_t b_off = (uint32_t)(b_row * (TS * 2) + ((lane >> 3) & 1) * 16);

    float acc[2][8][4];
#pragma unroll
    for (int i = 0; i < 2; ++i)
#pragma unroll
        for (int j = 0; j < 8; ++j)
#pragma unroll
            for (int c = 0; c < 4; ++c) acc[i][j][c] = 0.f;

    const int KT = K / BK;  // 128

    auto issue_stage = [&](int t) {
        const uint32_t st = sbase + (uint32_t)(t % STAGES) * STAGE_BYTES + sdst;
        const size_t kb = (size_t)t * BK;
        const __half* s0 = gA + kb;
        const __half* s1 = gB + kb;
        cp_async16(st + 0 * TILE_BYTES,      s0);
        cp_async16(st + 0 * TILE_BYTES + 16, s0 + 8);
        cp_async16(st + 1 * TILE_BYTES,      s1);
        cp_async16(st + 1 * TILE_BYTES + 16, s1 + 8);
        asm volatile("cp.async.commit_group;" ::: "memory");
    };

    issue_stage(0);
    issue_stage(1);
    issue_stage(2);

    for (int t = 0; t < KT; ++t) {
        asm volatile("cp.async.wait_group 2;" ::: "memory");
        __syncthreads();
        if (t + 3 < KT) issue_stage(t + 3);

        const uint32_t st = sbase + (uint32_t)(t % STAGES) * STAGE_BYTES;
        const uint32_t aAdr = st + 0 * TILE_BYTES + a_off;
        const uint32_t bAdr = st + 1 * TILE_BYTES + b_off;

#pragma unroll
        for (int ks = 0; ks < 2; ++ks) {
            const uint32_t koff = (uint32_t)(ks * 32);  // 16 halfs = 32B
            uint32_t af[2][4];
            ldmatrix_x4(af[0][0], af[0][1], af[0][2], af[0][3], aAdr + koff);
            ldmatrix_x4(af[1][0], af[1][1], af[1][2], af[1][3],
                        aAdr + koff + 16 * (TS * 2));
            uint32_t bf[4][4];
#pragma unroll
            for (int jp = 0; jp < 4; ++jp)
                ldmatrix_x4(bf[jp][0], bf[jp][1], bf[jp][2], bf[jp][3],
                            bAdr + koff + (uint32_t)(jp * 16 * (TS * 2)));
#pragma unroll
            for (int im = 0; im < 2; ++im)
#pragma unroll
                for (int jn = 0; jn < 8; ++jn) {
                    uint32_t breg[2] = { bf[jn >> 1][(jn & 1) * 2],
                                         bf[jn >> 1][(jn & 1) * 2 + 1] };
                    mma_f16(acc[im][jn], af[im], breg);
                }
        }
        __syncthreads();
    }

    // ---- epilogue: bias + store ----
    const int r_base = mtile * BM + wm * 32 + (lane >> 2);
    const int c_base = ntile * BN + wn * 64 + (lane & 3) * 2;
#pragma unroll
    for (int im = 0; im < 2; ++im) {
#pragma unroll
        for (int jn = 0; jn < 8; ++jn) {
            const int col = c_base + jn * 8;
            const float2 bv = *reinterpret_cast<const float2*>(Bv + col);
            const int r0 = r_base + im * 16;
            float2 o0 = make_float2(acc[im][jn][0] + bv.x, acc[im][jn][1] + bv.y);
            float2 o1 = make_float2(acc[im][jn][2] + bv.x, acc[im][jn][3] + bv.y);
            *reinterpret_cast<float2*>(O + (size_t)r0 * V + col)       = o0;
            *reinterpret_cast<float2*>(O + (size_t)(r0 + 8) * V + col) = o1;
        }
    }
}

// ---------------- launch --------------------------------------------------------
extern "C" void kernel_launch(void* const* d_in, const int* in_sizes, int n_in,
                              void* d_out, int out_size) {
    const float* X  = (const float*)d_in[0];  // [T, D]
    const float* W  = (const float*)d_in[1];  // [V, D]
    const float* Bv = (const float*)d_in[2];  // [V]
    float* O = (float*)d_out;                 // [T, V]

    const int V = in_sizes[2];
    const int D = in_sizes[1] / V;
    const int T = in_sizes[0] / D;

    const long nx4 = (long)T * D / 4;
    const long nw4 = (long)V * D / 4;
    conv_W_kernel<<<(unsigned)(nw4 / (NTHR * 4)), NTHR>>>((const float4*)W, nw4);
    conv_X_kernel<<<(unsigned)(nx4 / (NTHR * 4)), NTHR>>>((const float4*)X, nx4);

    cudaFuncSetAttribute(gemm_f16_kernel,
                         cudaFuncAttributeMaxDynamicSharedMemorySize, SMEM_NEED);
    dim3 grid(T / BM, V / BN);  // (16, 250); x fastest -> W tile reuse in L2
    gemm_f16_kernel<<<grid, NTHR, SMEM_NEED>>>(Bv, O, T, V, D);
}

// round 11
// speedup vs baseline: 1.5601x; 1.0241x over previous
#include <cuda_runtime.h>
#include <cuda_fp16.h>
#include <cstdint>

// RoutingLinear == GEMM + bias: O[t][v] = sum_d X[t][d]*W[v][d] + b[v]
// X[2048,4096] fp32, W[32000,4096] fp32, b[32000], O[2048,32000] fp32.
//
// Converged design (R7/R10 skeleton): fp16-in / fp32-accumulate legacy HMMA
// GEMM at the sm_103a non-tcgen05 tensor ceiling (~552 MAC/cyc/SM measured),
// DRAM-bound MLP=4 convert pre-pass (conv_W ~106us @ 88% DRAM).
//
// R11 delta (single, provably-safe change): remove the trailing
// __syncthreads in the k-loop. With the 4-stage ring, the leading sync
// (after cp.async.wait_group) already guarantees (a) stage-t visibility to
// all threads and (b) that all threads finished reading stage t-1 before
// issue_stage(t+3) overwrites slot (t-1)%4. 128 barriers/CTA deleted.

#define NTHR 256
#define BM 128
#define BN 128
#define BK 32
#define STAGES 4
#define TS 40                        // smem row stride in halfs (32 + 8 pad)
#define TILE_BYTES (BM * TS * 2)     // 10240
#define STAGE_BYTES (2 * TILE_BYTES) // A, B
#define SMEM_NEED (STAGES * STAGE_BYTES)  // 81920

#define T_MAX 2048
#define D_MAX 4096
#define V_MAX 32000

// ---------------- scratch (static device memory; no allocs allowed) ----------
__device__ __half g_Xh[(size_t)T_MAX * D_MAX];
__device__ __half g_Wh[(size_t)V_MAX * D_MAX];

// ---------------- helpers -----------------------------------------------------
__device__ __forceinline__ uint32_t smem_u32_of(const void* p) {
    uint32_t a;
    asm("{ .reg .u64 t; cvta.to.shared.u64 t, %1; cvt.u32.u64 %0, t; }"
        : "=r"(a) : "l"(p));
    return a;
}
__device__ __forceinline__ void cp_async16(uint32_t dst, const void* src) {
    asm volatile("cp.async.cg.shared.global [%0], [%1], 16;"
                 :: "r"(dst), "l"(src) : "memory");
}
__device__ __forceinline__ void ldmatrix_x4(uint32_t& r0, uint32_t& r1,
                                            uint32_t& r2, uint32_t& r3,
                                            uint32_t addr) {
    asm volatile("ldmatrix.sync.aligned.m8n8.x4.shared.b16 {%0,%1,%2,%3}, [%4];"
                 : "=r"(r0), "=r"(r1), "=r"(r2), "=r"(r3) : "r"(addr));
}
__device__ __forceinline__ void mma_f16(float* d, const uint32_t* a,
                                        const uint32_t* b) {
    asm volatile(
        "mma.sync.aligned.m16n8k16.row.col.f32.f16.f16.f32 "
        "{%0,%1,%2,%3}, {%4,%5,%6,%7}, {%8,%9}, {%0,%1,%2,%3};"
        : "+f"(d[0]), "+f"(d[1]), "+f"(d[2]), "+f"(d[3])
        : "r"(a[0]), "r"(a[1]), "r"(a[2]), "r"(a[3]), "r"(b[0]), "r"(b[1]));
}

// ---------------- convert kernels (MLP=4; grid*NTHR*4 == n4 exactly) -----------
__global__ void conv_X_kernel(const float4* __restrict__ src, long n4) {
    uint2* __restrict__ dst = reinterpret_cast<uint2*>(g_Xh);
    const long base = (long)blockIdx.x * (NTHR * 4) + threadIdx.x;
    float4 v[4];
#pragma unroll
    for (int k = 0; k < 4; ++k) v[k] = src[base + k * NTHR];
#pragma unroll
    for (int k = 0; k < 4; ++k) {
        __half2 h0 = __floats2half2_rn(v[k].x, v[k].y);
        __half2 h1 = __floats2half2_rn(v[k].z, v[k].w);
        dst[base + k * NTHR] = make_uint2(*(uint32_t*)&h0, *(uint32_t*)&h1);
    }
}
__global__ void conv_W_kernel(const float4* __restrict__ src, long n4) {
    uint2* __restrict__ dst = reinterpret_cast<uint2*>(g_Wh);
    const long base = (long)blockIdx.x * (NTHR * 4) + threadIdx.x;
    float4 v[4];
#pragma unroll
    for (int k = 0; k < 4; ++k) v[k] = src[base + k * NTHR];
#pragma unroll
    for (int k = 0; k < 4; ++k) {
        __half2 h0 = __floats2half2_rn(v[k].x, v[k].y);
        __half2 h1 = __floats2half2_rn(v[k].z, v[k].w);
        dst[base + k * NTHR] = make_uint2(*(uint32_t*)&h0, *(uint32_t*)&h1);
    }
}

// ---------------- GEMM ----------------------------------------------------------
__global__ __launch_bounds__(NTHR, 2)
void gemm_f16_kernel(const float* __restrict__ Bv,
                     float* __restrict__ O,
                     int T, int V, int K) {
    extern __shared__ char smem[];
    const uint32_t sbase = smem_u32_of(smem);

    const int tid  = threadIdx.x;
    const int wid  = tid >> 5;
    const int lane = tid & 31;
    const int wm   = wid & 3;      // 4 m-groups of 32 rows
    const int wn   = wid >> 2;     // 2 n-groups of 64 cols
    const int mtile = blockIdx.x;
    const int ntile = blockIdx.y;

    // ---- gmem sources for cp.async staging ----
    const int srow = tid >> 1;           // 0..127
    const int shalf = (tid & 1) * 16;    // half-element offset within 32-elem row
    const __half* gA = g_Xh + (size_t)(mtile * BM + srow) * K + shalf;
    const __half* gB = g_Wh + (size_t)(ntile * BN + srow) * K + shalf;
    const uint32_t sdst = (uint32_t)(srow * (TS * 2) + (tid & 1) * 32);

    // ---- ldmatrix per-lane base offsets (bytes, relative to tile base) ----
    const int a_row = wm * 32 + (lane & 7) + ((lane >> 3) & 1) * 8;
    const uint32_t a_off = (uint32_t)(a_row * (TS * 2) + (lane >> 4) * 16);
    const int b_row = wn * 64 + (lane & 7) + ((lane >> 4) & 1) * 8;
    const uint32_t b_off = (uint32_t)(b_row * (TS * 2) + ((lane >> 3) & 1) * 16);

    float acc[2][8][4];
#pragma unroll
    for (int i = 0; i < 2; ++i)
#pragma unroll
        for (int j = 0; j < 8; ++j)
#pragma unroll
            for (int c = 0; c < 4; ++c) acc[i][j][c] = 0.f;

    const int KT = K / BK;  // 128

    auto issue_stage = [&](int t) {
        const uint32_t st = sbase + (uint32_t)(t % STAGES) * STAGE_BYTES + sdst;
        const size_t kb = (size_t)t * BK;
        const __half* s0 = gA + kb;
        const __half* s1 = gB + kb;
        cp_async16(st + 0 * TILE_BYTES,      s0);
        cp_async16(st + 0 * TILE_BYTES + 16, s0 + 8);
        cp_async16(st + 1 * TILE_BYTES,      s1);
        cp_async16(st + 1 * TILE_BYTES + 16, s1 + 8);
        asm volatile("cp.async.commit_group;" ::: "memory");
    };

    issue_stage(0);
    issue_stage(1);
    issue_stage(2);

    for (int t = 0; t < KT; ++t) {
        asm volatile("cp.async.wait_group 2;" ::: "memory");
        __syncthreads();   // publishes stage t to all threads AND proves all
                           // threads finished reading stage t-1 (their iter
                           // t-1 compute precedes this barrier) -> safe to
                           // overwrite slot (t+3)%4 == (t-1)%4 below.
        if (t + 3 < KT) issue_stage(t + 3);

        const uint32_t st = sbase + (uint32_t)(t % STAGES) * STAGE_BYTES;
        const uint32_t aAdr = st + 0 * TILE_BYTES + a_off;
        const uint32_t bAdr = st + 1 * TILE_BYTES + b_off;

#pragma unroll
        for (int ks = 0; ks < 2; ++ks) {
            const uint32_t koff = (uint32_t)(ks * 32);  // 16 halfs = 32B
            uint32_t af[2][4];
            ldmatrix_x4(af[0][0], af[0][1], af[0][2], af[0][3], aAdr + koff);
            ldmatrix_x4(af[1][0], af[1][1], af[1][2], af[1][3],
                        aAdr + koff + 16 * (TS * 2));
            uint32_t bf[4][4];
#pragma unroll
            for (int jp = 0; jp < 4; ++jp)
                ldmatrix_x4(bf[jp][0], bf[jp][1], bf[jp][2], bf[jp][3],
                            bAdr + koff + (uint32_t)(jp * 16 * (TS * 2)));
#pragma unroll
            for (int im = 0; im < 2; ++im)
#pragma unroll
                for (int jn = 0; jn < 8; ++jn) {
                    uint32_t breg[2] = { bf[jn >> 1][(jn & 1) * 2],
                                         bf[jn >> 1][(jn & 1) * 2 + 1] };
                    mma_f16(acc[im][jn], af[im], breg);
                }
        }
        // trailing __syncthreads removed: next iteration's leading barrier
        // provides the write-after-read protection (see comment above).
    }

    // ---- epilogue: bias + store (registers only; no smem dependence) ----
    const int r_base = mtile * BM + wm * 32 + (lane >> 2);
    const int c_base = ntile * BN + wn * 64 + (lane & 3) * 2;
#pragma unroll
    for (int im = 0; im < 2; ++im) {
#pragma unroll
        for (int jn = 0; jn < 8; ++jn) {
            const int col = c_base + jn * 8;
            const float2 bv = *reinterpret_cast<const float2*>(Bv + col);
            const int r0 = r_base + im * 16;
            float2 o0 = make_float2(acc[im][jn][0] + bv.x, acc[im][jn][1] + bv.y);
            float2 o1 = make_float2(acc[im][jn][2] + bv.x, acc[im][jn][3] + bv.y);
            *reinterpret_cast<float2*>(O + (size_t)r0 * V + col)       = o0;
            *reinterpret_cast<float2*>(O + (size_t)(r0 + 8) * V + col) = o1;
        }
    }
}

// ---------------- launch --------------------------------------------------------
extern "C" void kernel_launch(void* const* d_in, const int* in_sizes, int n_in,
                              void* d_out, int out_size) {
    const float* X  = (const float*)d_in[0];  // [T, D]
    const float* W  = (const float*)d_in[1];  // [V, D]
    const float* Bv = (const float*)d_in[2];  // [V]
    float* O = (float*)d_out;                 // [T, V]

    const int V = in_sizes[2];
    const int D = in_sizes[1] / V;
    const int T = in_sizes[0] / D;

    const long nx4 = (long)T * D / 4;
    const long nw4 = (long)V * D / 4;
    conv_W_kernel<<<(unsigned)(nw4 / (NTHR * 4)), NTHR>>>((const float4*)W, nw4);
    conv_X_kernel<<<(unsigned)(nx4 / (NTHR * 4)), NTHR>>>((const float4*)X, nx4);

    cudaFuncSetAttribute(gemm_f16_kernel,
                         cudaFuncAttributeMaxDynamicSharedMemorySize, SMEM_NEED);
    dim3 grid(T / BM, V / BN);  // (16, 250); x fastest -> W tile reuse in L2
    gemm_f16_kernel<<<grid, NTHR, SMEM_NEED>>>(Bv, O, T, V, D);
}

// round 12
// speedup vs baseline: 1.6094x; 1.0316x over previous
#include <cuda_runtime.h>
#include <cuda_fp16.h>
#include <cstdint>

// RoutingLinear == GEMM + bias: O[t][v] = sum_d X[t][d]*W[v][d] + b[v]
// X[2048,4096] fp32, W[32000,4096] fp32, b[32000], O[2048,32000] fp32.
//
// R12: same validated fp16/FP32-accum HMMA skeleton (BK=32, 4-stage cp.async,
// TS=40, single leading sync per iter), but CTA tile 128x64 with 3 CTAs/SM:
//   - 8000 tiles over 444 resident CTAs -> smaller ragged finish,
//   - 24 warps/SM (6/SMSP) -> more independent issue streams for HMMA,
//   - stage = A(10240B) + B(5120B) = 15360B, 4 stages = 61440B/CTA.
// Warp layout: 4m x 2n, warp tile 32x32, acc = 32 regs.

#define NTHR 256
#define BM 128
#define BN 64
#define BK 32
#define STAGES 4
#define TS 40                         // smem row stride in halfs (32 + 8 pad)
#define TILE_A_BYTES (BM * TS * 2)    // 10240
#define TILE_B_BYTES (BN * TS * 2)    // 5120
#define STAGE_BYTES (TILE_A_BYTES + TILE_B_BYTES)  // 15360
#define SMEM_NEED (STAGES * STAGE_BYTES)           // 61440

#define T_MAX 2048
#define D_MAX 4096
#define V_MAX 32000

// ---------------- scratch (static device memory; no allocs allowed) ----------
__device__ __half g_Xh[(size_t)T_MAX * D_MAX];
__device__ __half g_Wh[(size_t)V_MAX * D_MAX];

// ---------------- helpers -----------------------------------------------------
__device__ __forceinline__ uint32_t smem_u32_of(const void* p) {
    uint32_t a;
    asm("{ .reg .u64 t; cvta.to.shared.u64 t, %1; cvt.u32.u64 %0, t; }"
        : "=r"(a) : "l"(p));
    return a;
}
__device__ __forceinline__ void cp_async16(uint32_t dst, const void* src) {
    asm volatile("cp.async.cg.shared.global [%0], [%1], 16;"
                 :: "r"(dst), "l"(src) : "memory");
}
__device__ __forceinline__ void ldmatrix_x4(uint32_t& r0, uint32_t& r1,
                                            uint32_t& r2, uint32_t& r3,
                                            uint32_t addr) {
    asm volatile("ldmatrix.sync.aligned.m8n8.x4.shared.b16 {%0,%1,%2,%3}, [%4];"
                 : "=r"(r0), "=r"(r1), "=r"(r2), "=r"(r3) : "r"(addr));
}
__device__ __forceinline__ void mma_f16(float* d, const uint32_t* a,
                                        const uint32_t* b) {
    asm volatile(
        "mma.sync.aligned.m16n8k16.row.col.f32.f16.f16.f32 "
        "{%0,%1,%2,%3}, {%4,%5,%6,%7}, {%8,%9}, {%0,%1,%2,%3};"
        : "+f"(d[0]), "+f"(d[1]), "+f"(d[2]), "+f"(d[3])
        : "r"(a[0]), "r"(a[1]), "r"(a[2]), "r"(a[3]), "r"(b[0]), "r"(b[1]));
}

// ---------------- convert kernels (MLP=4; grid*NTHR*4 == n4 exactly) -----------
__global__ void conv_X_kernel(const float4* __restrict__ src, long n4) {
    uint2* __restrict__ dst = reinterpret_cast<uint2*>(g_Xh);
    const long base = (long)blockIdx.x * (NTHR * 4) + threadIdx.x;
    float4 v[4];
#pragma unroll
    for (int k = 0; k < 4; ++k) v[k] = src[base + k * NTHR];
#pragma unroll
    for (int k = 0; k < 4; ++k) {
        __half2 h0 = __floats2half2_rn(v[k].x, v[k].y);
        __half2 h1 = __floats2half2_rn(v[k].z, v[k].w);
        dst[base + k * NTHR] = make_uint2(*(uint32_t*)&h0, *(uint32_t*)&h1);
    }
}
__global__ void conv_W_kernel(const float4* __restrict__ src, long n4) {
    uint2* __restrict__ dst = reinterpret_cast<uint2*>(g_Wh);
    const long base = (long)blockIdx.x * (NTHR * 4) + threadIdx.x;
    float4 v[4];
#pragma unroll
    for (int k = 0; k < 4; ++k) v[k] = src[base + k * NTHR];
#pragma unroll
    for (int k = 0; k < 4; ++k) {
        __half2 h0 = __floats2half2_rn(v[k].x, v[k].y);
        __half2 h1 = __floats2half2_rn(v[k].z, v[k].w);
        dst[base + k * NTHR] = make_uint2(*(uint32_t*)&h0, *(uint32_t*)&h1);
    }
}

// ---------------- GEMM ----------------------------------------------------------
__global__ __launch_bounds__(NTHR, 3)
void gemm_f16_kernel(const float* __restrict__ Bv,
                     float* __restrict__ O,
                     int T, int V, int K) {
    extern __shared__ char smem[];
    const uint32_t sbase = smem_u32_of(smem);

    const int tid  = threadIdx.x;
    const int wid  = tid >> 5;
    const int lane = tid & 31;
    const int wm   = wid & 3;      // 4 m-groups of 32 rows
    const int wn   = wid >> 2;     // 2 n-groups of 32 cols
    const int mtile = blockIdx.x;
    const int ntile = blockIdx.y;

    // ---- staging: A = 128 rows x 4 segs (2/thread), B = 64 rows x 4 segs (1/thread)
    const int srowA = tid >> 2;          // 0..63 (A rows: srowA and srowA+64)
    const int seg   = tid & 3;           // 16B segment within 32-half row
    const __half* gA0 = g_Xh + (size_t)(mtile * BM + srowA) * K + seg * 8;
    const __half* gA1 = gA0 + (size_t)64 * K;
    const __half* gB  = g_Wh + (size_t)(ntile * BN + srowA) * K + seg * 8;
    const uint32_t sdstA0 = (uint32_t)(srowA * (TS * 2) + seg * 16);
    const uint32_t sdstA1 = sdstA0 + 64 * (TS * 2);
    const uint32_t sdstB  = sdstA0;      // same row/seg mapping inside B tile

    // ---- ldmatrix per-lane base offsets (bytes, relative to tile bases) ----
    const int a_row = wm * 32 + (lane & 7) + ((lane >> 3) & 1) * 8;
    const uint32_t a_off = (uint32_t)(a_row * (TS * 2) + (lane >> 4) * 16);
    const int b_row = wn * 32 + (lane & 7) + ((lane >> 4) & 1) * 8;
    const uint32_t b_off = (uint32_t)(b_row * (TS * 2) + ((lane >> 3) & 1) * 16);

    float acc[2][4][4];
#pragma unroll
    for (int i = 0; i < 2; ++i)
#pragma unroll
        for (int j = 0; j < 4; ++j)
#pragma unroll
            for (int c = 0; c < 4; ++c) acc[i][j][c] = 0.f;

    const int KT = K / BK;  // 128

    auto issue_stage = [&](int t) {
        const uint32_t st = sbase + (uint32_t)(t % STAGES) * STAGE_BYTES;
        const size_t kb = (size_t)t * BK;
        cp_async16(st + sdstA0,               gA0 + kb);
        cp_async16(st + sdstA1,               gA1 + kb);
        cp_async16(st + TILE_A_BYTES + sdstB, gB + kb);
        asm volatile("cp.async.commit_group;" ::: "memory");
    };

    issue_stage(0);
    issue_stage(1);
    issue_stage(2);

    for (int t = 0; t < KT; ++t) {
        asm volatile("cp.async.wait_group 2;" ::: "memory");
        __syncthreads();   // stage t visible; all threads past iter t-1 reads
        if (t + 3 < KT) issue_stage(t + 3);

        const uint32_t st = sbase + (uint32_t)(t % STAGES) * STAGE_BYTES;
        const uint32_t aAdr = st + a_off;
        const uint32_t bAdr = st + TILE_A_BYTES + b_off;

#pragma unroll
        for (int ks = 0; ks < 2; ++ks) {
            const uint32_t koff = (uint32_t)(ks * 32);  // 16 halfs = 32B
            uint32_t af[2][4];
            ldmatrix_x4(af[0][0], af[0][1], af[0][2], af[0][3], aAdr + koff);
            ldmatrix_x4(af[1][0], af[1][1], af[1][2], af[1][3],
                        aAdr + koff + 16 * (TS * 2));
            uint32_t bf[2][4];
#pragma unroll
            for (int jp = 0; jp < 2; ++jp)
                ldmatrix_x4(bf[jp][0], bf[jp][1], bf[jp][2], bf[jp][3],
                            bAdr + koff + (uint32_t)(jp * 16 * (TS * 2)));
#pragma unroll
            for (int im = 0; im < 2; ++im)
#pragma unroll
                for (int jn = 0; jn < 4; ++jn) {
                    uint32_t breg[2] = { bf[jn >> 1][(jn & 1) * 2],
                                         bf[jn >> 1][(jn & 1) * 2 + 1] };
                    mma_f16(acc[im][jn], af[im], breg);
                }
        }
        // single sync per iter (R11-validated): next leading barrier protects
        // slot reuse.
    }

    // ---- epilogue: bias + store ----
    const int r_base = mtile * BM + wm * 32 + (lane >> 2);
    const int c_base = ntile * BN + wn * 32 + (lane & 3) * 2;
#pragma unroll
    for (int im = 0; im < 2; ++im) {
#pragma unroll
        for (int jn = 0; jn < 4; ++jn) {
            const int col = c_base + jn * 8;
            const float2 bv = *reinterpret_cast<const float2*>(Bv + col);
            const int r0 = r_base + im * 16;
            float2 o0 = make_float2(acc[im][jn][0] + bv.x, acc[im][jn][1] + bv.y);
            float2 o1 = make_float2(acc[im][jn][2] + bv.x, acc[im][jn][3] + bv.y);
            *reinterpret_cast<float2*>(O + (size_t)r0 * V + col)       = o0;
            *reinterpret_cast<float2*>(O + (size_t)(r0 + 8) * V + col) = o1;
        }
    }
}

// ---------------- launch --------------------------------------------------------
extern "C" void kernel_launch(void* const* d_in, const int* in_sizes, int n_in,
                              void* d_out, int out_size) {
    const float* X  = (const float*)d_in[0];  // [T, D]
    const float* W  = (const float*)d_in[1];  // [V, D]
    const float* Bv = (const float*)d_in[2];  // [V]
    float* O = (float*)d_out;                 // [T, V]

    const int V = in_sizes[2];
    const int D = in_sizes[1] / V;
    const int T = in_sizes[0] / D;

    const long nx4 = (long)T * D / 4;
    const long nw4 = (long)V * D / 4;
    conv_W_kernel<<<(unsigned)(nw4 / (NTHR * 4)), NTHR>>>((const float4*)W, nw4);
    conv_X_kernel<<<(unsigned)(nx4 / (NTHR * 4)), NTHR>>>((const float4*)X, nx4);

    cudaFuncSetAttribute(gemm_f16_kernel,
                         cudaFuncAttributeMaxDynamicSharedMemorySize, SMEM_NEED);
    dim3 grid(T / BM, V / BN);  // (16, 500); x fastest -> W tile reuse in L2
    gemm_f16_kernel<<<grid, NTHR, SMEM_NEED>>>(Bv, O, T, V, D);
}